// round 16
// baseline (speedup 1.0000x reference)
#include <cuda_runtime.h>

#define Nn   16000
#define Ee   48000
#define Ff   32000
#define Gg   32
#define Dd   64
#define NBUMP 32
#define HIDN  256
#define NCLS  10

#define STRIP 128
#define NSN (Nn / STRIP)            // 125
#define NSE (Ee / STRIP)            // 375
#define NSF (Ff / STRIP)            // 250
#define TOTS (NSN + NSE + NSF)      // 750  (x2 dir-halves = 1500 warps)
#define TMAIN 128                   // 4 warps/block -> 375 blocks

#define ETILE 512
#define EBLK ((Ee + ETILE - 1) / ETILE)   // 94
#define FBLK ((Ff + ETILE - 1) / ETILE)   // 63

// ---------------- scratch (static device globals) ----------------
__device__ float4 d_nh4[Nn * 16];        // node-major heights; float view: [n*64 + d]
__device__ int4   d_epk[Ee];             // {e0, e1, g, w_bits} graph-sorted
__device__ int4   d_fpk[Ff];             // {f0, f1, f2, g} graph-sorted
__device__ float  d_fsw[Ff];
__device__ int    d_ncnt[Gg], d_ecnt[Gg], d_fcnt[Gg];
__device__ int    d_ecur[Gg], d_fcur[Gg];
__device__ int    d_netc[Gg];
__device__ float  d_accS[Gg * NBUMP * Dd];   // signed tanh sums [g][bump][d]

// ---------------- launch 1: node heights + zero counters/acc ----------------
__global__ void nh_kernel(const float* __restrict__ x,
                          const float* __restrict__ nw,
                          const float* __restrict__ v) {
    __shared__ float sv[3 * Dd];
    if (threadIdx.x < 3 * Dd) sv[threadIdx.x] = v[threadIdx.x];
    __syncthreads();

    int tid = blockIdx.x * blockDim.x + threadIdx.x;
    int nthreads = gridDim.x * blockDim.x;
    for (int i = tid; i < Gg * NBUMP * Dd; i += nthreads) d_accS[i] = 0.f;
    if (tid < Gg) { d_ncnt[tid] = 0; d_ecnt[tid] = 0; d_fcnt[tid] = 0; }

    int n = tid;
    if (n >= Nn) return;
    float x0 = x[3 * n], x1 = x[3 * n + 1], x2 = x[3 * n + 2];
    float w = nw[n];
    #pragma unroll
    for (int c = 0; c < 16; c++) {
        float4 h;
        int d = c * 4;
        h.x = w * (x0 * sv[d + 0] + x1 * sv[Dd + d + 0] + x2 * sv[2 * Dd + d + 0]);
        h.y = w * (x0 * sv[d + 1] + x1 * sv[Dd + d + 1] + x2 * sv[2 * Dd + d + 1]);
        h.z = w * (x0 * sv[d + 2] + x1 * sv[Dd + d + 2] + x2 * sv[2 * Dd + d + 2]);
        h.w = w * (x0 * sv[d + 3] + x1 * sv[Dd + d + 3] + x2 * sv[2 * Dd + d + 3]);
        d_nh4[n * 16 + c] = h;
    }
}

// ---------------- launch 2: histograms via shared memory ----------------
__global__ void prep_kernel(const int* __restrict__ bid,
                            const int* __restrict__ ei,
                            const int* __restrict__ fc) {
    __shared__ int sn[Gg], se[Gg], sf[Gg];
    int t = threadIdx.x;
    if (t < Gg) { sn[t] = 0; se[t] = 0; sf[t] = 0; }
    __syncthreads();
    int stride = gridDim.x * blockDim.x;
    int i0 = blockIdx.x * blockDim.x + t;
    for (int i = i0; i < Nn; i += stride) atomicAdd(&sn[bid[i]], 1);
    for (int i = i0; i < Ee; i += stride) atomicAdd(&se[bid[ei[i]]], 1);
    for (int i = i0; i < Ff; i += stride) atomicAdd(&sf[bid[fc[i]]], 1);
    __syncthreads();
    if (t < Gg) {
        if (sn[t]) atomicAdd(&d_ncnt[t], sn[t]);
        if (se[t]) atomicAdd(&d_ecnt[t], se[t]);
        if (sf[t]) atomicAdd(&d_fcnt[t], sf[t]);
    }
}

// ---------------- launch 3: exclusive scan + Euler counts ----------------
__global__ void scan_kernel() {
    if (threadIdx.x == 0) {
        int ea = 0, fa = 0;
        for (int g = 0; g < Gg; g++) {
            d_ecur[g] = ea; ea += d_ecnt[g];
            d_fcur[g] = fa; fa += d_fcnt[g];
            d_netc[g] = d_ncnt[g] - d_ecnt[g] + d_fcnt[g];
        }
    }
}

// ---------------- launch 4: counting-sort scatter, block-aggregated atomics ----------------
__global__ void __launch_bounds__(256) scatter_kernel(
        const int* __restrict__ ei, const float* __restrict__ ew,
        const int* __restrict__ fc, const float* __restrict__ fw,
        const int* __restrict__ bid) {
    __shared__ int scnt[Gg], sbase[Gg], sloc[Gg];
    int t = threadIdx.x;
    if (t < Gg) { scnt[t] = 0; sloc[t] = 0; }
    __syncthreads();

    if (blockIdx.x < EBLK) {
        int base = blockIdx.x * ETILE;
        int e0r[2], e1r[2], gr[2]; float wr[2];
        #pragma unroll
        for (int j = 0; j < 2; j++) {
            int i = base + t + j * 256;
            if (i < Ee) {
                e0r[j] = ei[i]; e1r[j] = ei[Ee + i]; wr[j] = ew[i];
                gr[j] = bid[e0r[j]];
                atomicAdd(&scnt[gr[j]], 1);
            } else gr[j] = -1;
        }
        __syncthreads();
        if (t < Gg && scnt[t]) sbase[t] = atomicAdd(&d_ecur[t], scnt[t]);
        __syncthreads();
        #pragma unroll
        for (int j = 0; j < 2; j++) if (gr[j] >= 0) {
            int pos = sbase[gr[j]] + atomicAdd(&sloc[gr[j]], 1);
            d_epk[pos] = make_int4(e0r[j], e1r[j], gr[j], __float_as_int(wr[j]));
        }
    } else {
        int base = (blockIdx.x - EBLK) * ETILE;
        int f0r[2], f1r[2], f2r[2], gr[2]; float wr[2];
        #pragma unroll
        for (int j = 0; j < 2; j++) {
            int i = base + t + j * 256;
            if (i < Ff) {
                f0r[j] = fc[i]; f1r[j] = fc[Ff + i]; f2r[j] = fc[2 * Ff + i]; wr[j] = fw[i];
                gr[j] = bid[f0r[j]];
                atomicAdd(&scnt[gr[j]], 1);
            } else gr[j] = -1;
        }
        __syncthreads();
        if (t < Gg && scnt[t]) sbase[t] = atomicAdd(&d_fcur[t], scnt[t]);
        __syncthreads();
        #pragma unroll
        for (int j = 0; j < 2; j++) if (gr[j] >= 0) {
            int pos = sbase[gr[j]] + atomicAdd(&sloc[gr[j]], 1);
            d_fpk[pos] = make_int4(f0r[j], f1r[j], f2r[j], gr[j]);
            d_fsw[pos] = wr[j];
        }
    }
}

__device__ __forceinline__ float tanha(float z) {
    float r;
    asm("tanh.approx.f32 %0, %1;" : "=f"(r) : "f"(z));
    return r;
}

// ---------------- launch 5: main ECC accumulation ----------------
// lane = direction (within 32-dir half). Per element: 4 tanh in a window around
// the threshold crossing; saturated tails handled analytically via a per-thread
// difference array in shared memory (prefix-summed at graph-boundary flush).
__global__ void __launch_bounds__(TMAIN) main_kernel(const int* __restrict__ bid) {
    __shared__ float sd[TMAIN * 33];
    float* md = &sd[threadIdx.x * 33];
    #pragma unroll
    for (int b = 0; b < 33; b++) md[b] = 0.f;

    const int wid  = blockIdx.x * (TMAIN / 32) + (threadIdx.x >> 5);
    const int lane = threadIdx.x & 31;
    if (wid >= 2 * TOTS) return;
    const int doff = (wid & 1) * 32 + lane;
    int s = wid >> 1;
    int stream, strip;
    if (s < NSN)            { stream = 0; strip = s; }
    else if (s < NSN + NSE) { stream = 1; strip = s - NSN; }
    else                    { stream = 2; strip = s - NSN - NSE; }

    const int begin = strip * STRIP;
    const float* __restrict__ nhf = (const float*)d_nh4;
    const float sign = (stream == 1) ? -1.f : 1.f;
    const float STEP = 100.f / 31.f;

    int gcur = -1;
    int cnt = 0;

    #define FLUSH() do {                                                      \
        float run = -(float)cnt;                                              \
        float* p = &d_accS[gcur * (NBUMP * Dd) + doff];                       \
        _Pragma("unroll")                                                     \
        for (int b = 0; b < NBUMP; b++) {                                     \
            run += md[b]; md[b] = 0.f;                                        \
            atomicAdd(p + b * Dd, sign * run);                                \
        }                                                                     \
        md[32] = 0.f; cnt = 0; } while (0)

    for (int base = begin; base < begin + STRIP; base += 4) {
        float h4[4]; int g4[4];
        #pragma unroll
        for (int j = 0; j < 4; j++) {
            int i = base + j;
            if (stream == 0) {
                g4[j] = bid[i];
                h4[j] = nhf[i * 64 + doff];
            } else if (stream == 1) {
                int4 e = d_epk[i];
                g4[j] = e.z;
                h4[j] = fmaxf(nhf[e.x * 64 + doff], nhf[e.y * 64 + doff])
                        * __int_as_float(e.w);
            } else {
                int4 f = d_fpk[i];
                g4[j] = f.w;
                h4[j] = fmaxf(fmaxf(nhf[f.x * 64 + doff], nhf[f.y * 64 + doff]),
                              nhf[f.z * 64 + doff]) * d_fsw[i];
            }
        }
        #pragma unroll
        for (int j = 0; j < 4; j++) {
            if (g4[j] != gcur) {              // lane-uniform branch
                if (gcur >= 0) FLUSH();
                gcur = g4[j];
            }
            float h = h4[j];
            int b0 = (int)floorf((h + 1.f) * 15.5f) - 1;
            b0 = min(max(b0, 0), 28);
            float z = STEP * (float)b0 - 50.f - 50.f * h;
            float t0 = tanha(z);
            float t1 = tanha(z + STEP);
            float t2 = tanha(z + 2.f * STEP);
            float t3 = tanha(z + 3.f * STEP);
            md[b0]     += t0 + 1.f;
            md[b0 + 1] += t1 - t0;
            md[b0 + 2] += t2 - t1;
            md[b0 + 3] += t3 - t2;
            md[b0 + 4] += 1.f - t3;
            cnt++;
        }
    }
    if (gcur >= 0) FLUSH();
    #undef FLUSH
}

// ---------------- launch 6: finalize ecc + MLP, fused ----------------
__global__ void mlp_kernel(const float* __restrict__ W1, const float* __restrict__ b1,
                           const float* __restrict__ W2, const float* __restrict__ b2,
                           float* __restrict__ out) {
    __shared__ float sflat[NBUMP * Dd];
    __shared__ float sh[HIDN];
    int g = blockIdx.x;
    float halfnet = 0.5f * (float)d_netc[g];
    float* flat_out = out + Gg * NCLS + g * (NBUMP * Dd);
    const float* acc = d_accS + g * (NBUMP * Dd);
    for (int i = threadIdx.x; i < NBUMP * Dd; i += blockDim.x) {
        float val = halfnet + 0.5f * acc[i];
        sflat[i] = val;
        flat_out[i] = val;
    }
    __syncthreads();

    int warp = threadIdx.x >> 5, lane = threadIdx.x & 31;
    for (int hh = warp; hh < HIDN; hh += 8) {
        const float* wrow = W1 + hh * (NBUMP * Dd);
        float p = 0.f;
        #pragma unroll 8
        for (int k = lane; k < NBUMP * Dd; k += 32) p += wrow[k] * sflat[k];
        #pragma unroll
        for (int o = 16; o; o >>= 1) p += __shfl_down_sync(0xffffffffu, p, o);
        if (lane == 0) sh[hh] = fmaxf(p + b1[hh], 0.f);
    }
    __syncthreads();
    if (warp == 0) {
        for (int c = 0; c < NCLS; c++) {
            float p = 0.f;
            #pragma unroll
            for (int k = lane; k < HIDN; k += 32) p += W2[c * HIDN + k] * sh[k];
            #pragma unroll
            for (int o = 16; o; o >>= 1) p += __shfl_down_sync(0xffffffffu, p, o);
            if (lane == 0) out[g * NCLS + c] = p + b2[c];
        }
    }
}

// ---------------- launch ----------------
extern "C" void kernel_launch(void* const* d_in, const int* in_sizes, int n_in,
                              void* d_out, int out_size) {
    const float* x   = (const float*)d_in[0];
    const float* nw  = (const float*)d_in[1];
    const float* ew  = (const float*)d_in[2];
    const float* fw  = (const float*)d_in[3];
    const float* v   = (const float*)d_in[4];
    const float* W1  = (const float*)d_in[5];
    const float* b1  = (const float*)d_in[6];
    const float* W2  = (const float*)d_in[7];
    const float* b2  = (const float*)d_in[8];
    const int*   ei  = (const int*)d_in[9];
    const int*   fc  = (const int*)d_in[10];
    const int*   bid = (const int*)d_in[11];
    float* out = (float*)d_out;

    nh_kernel<<<(Nn + 255) / 256, 256>>>(x, nw, v);
    prep_kernel<<<128, 256>>>(bid, ei, fc);
    scan_kernel<<<1, 32>>>();
    scatter_kernel<<<EBLK + FBLK, 256>>>(ei, ew, fc, fw, bid);

    main_kernel<<<(2 * TOTS + (TMAIN / 32) - 1) / (TMAIN / 32), TMAIN>>>(bid);

    mlp_kernel<<<Gg, 256>>>(W1, b1, W2, b2, out);
}

// round 17
// speedup vs baseline: 1.5034x; 1.5034x over previous
#include <cuda_runtime.h>

#define Nn   16000
#define Ee   48000
#define Ff   32000
#define Gg   32
#define Dd   64
#define NBUMP 32
#define HIDN  256
#define NCLS  10

#define STRIP 64
#define NSN (Nn / STRIP)            // 250
#define NSE (Ee / STRIP)            // 750
#define NSF (Ff / STRIP)            // 500
#define TOTS (NSN + NSE + NSF)      // 1500 (x2 dir-halves = 3000 warps)
#define TMAIN 128                   // 4 warps/block -> 750 blocks

#define ETILE 512
#define EBLK ((Ee + ETILE - 1) / ETILE)   // 94
#define FBLK ((Ff + ETILE - 1) / ETILE)   // 63

// ---------------- scratch (static device globals) ----------------
__device__ float4 d_nh4[Nn * 16];        // node-major heights; float view: [n*64 + d]
__device__ int4   d_epk[Ee];             // {e0, e1, g, w_bits} graph-sorted
__device__ int4   d_fpk[Ff];             // {f0, f1, f2, g} graph-sorted
__device__ float  d_fsw[Ff];
__device__ int    d_ncnt[Gg], d_ecnt[Gg], d_fcnt[Gg];
__device__ int    d_ecur[Gg], d_fcur[Gg];
__device__ int    d_netc[Gg];
__device__ float  d_accS[Gg * NBUMP * Dd];   // signed tanh sums [g][bump][d]

// ---------------- launch 1: node heights + zero counters/acc ----------------
__global__ void nh_kernel(const float* __restrict__ x,
                          const float* __restrict__ nw,
                          const float* __restrict__ v) {
    __shared__ float sv[3 * Dd];
    if (threadIdx.x < 3 * Dd) sv[threadIdx.x] = v[threadIdx.x];
    __syncthreads();

    int tid = blockIdx.x * blockDim.x + threadIdx.x;
    int nthreads = gridDim.x * blockDim.x;
    for (int i = tid; i < Gg * NBUMP * Dd; i += nthreads) d_accS[i] = 0.f;
    if (tid < Gg) { d_ncnt[tid] = 0; d_ecnt[tid] = 0; d_fcnt[tid] = 0; }

    int n = tid;
    if (n >= Nn) return;
    float x0 = x[3 * n], x1 = x[3 * n + 1], x2 = x[3 * n + 2];
    float w = nw[n];
    #pragma unroll
    for (int c = 0; c < 16; c++) {
        float4 h;
        int d = c * 4;
        h.x = w * (x0 * sv[d + 0] + x1 * sv[Dd + d + 0] + x2 * sv[2 * Dd + d + 0]);
        h.y = w * (x0 * sv[d + 1] + x1 * sv[Dd + d + 1] + x2 * sv[2 * Dd + d + 1]);
        h.z = w * (x0 * sv[d + 2] + x1 * sv[Dd + d + 2] + x2 * sv[2 * Dd + d + 2]);
        h.w = w * (x0 * sv[d + 3] + x1 * sv[Dd + d + 3] + x2 * sv[2 * Dd + d + 3]);
        d_nh4[n * 16 + c] = h;
    }
}

// ---------------- launch 2: histograms via shared memory ----------------
__global__ void prep_kernel(const int* __restrict__ bid,
                            const int* __restrict__ ei,
                            const int* __restrict__ fc) {
    __shared__ int sn[Gg], se[Gg], sf[Gg];
    int t = threadIdx.x;
    if (t < Gg) { sn[t] = 0; se[t] = 0; sf[t] = 0; }
    __syncthreads();
    int stride = gridDim.x * blockDim.x;
    int i0 = blockIdx.x * blockDim.x + t;
    for (int i = i0; i < Nn; i += stride) atomicAdd(&sn[bid[i]], 1);
    for (int i = i0; i < Ee; i += stride) atomicAdd(&se[bid[ei[i]]], 1);
    for (int i = i0; i < Ff; i += stride) atomicAdd(&sf[bid[fc[i]]], 1);
    __syncthreads();
    if (t < Gg) {
        if (sn[t]) atomicAdd(&d_ncnt[t], sn[t]);
        if (se[t]) atomicAdd(&d_ecnt[t], se[t]);
        if (sf[t]) atomicAdd(&d_fcnt[t], sf[t]);
    }
}

// ---------------- launch 3: exclusive scan + Euler counts ----------------
__global__ void scan_kernel() {
    if (threadIdx.x == 0) {
        int ea = 0, fa = 0;
        for (int g = 0; g < Gg; g++) {
            d_ecur[g] = ea; ea += d_ecnt[g];
            d_fcur[g] = fa; fa += d_fcnt[g];
            d_netc[g] = d_ncnt[g] - d_ecnt[g] + d_fcnt[g];
        }
    }
}

// ---------------- launch 4: counting-sort scatter, block-aggregated atomics ----------------
__global__ void __launch_bounds__(256) scatter_kernel(
        const int* __restrict__ ei, const float* __restrict__ ew,
        const int* __restrict__ fc, const float* __restrict__ fw,
        const int* __restrict__ bid) {
    __shared__ int scnt[Gg], sbase[Gg], sloc[Gg];
    int t = threadIdx.x;
    if (t < Gg) { scnt[t] = 0; sloc[t] = 0; }
    __syncthreads();

    if (blockIdx.x < EBLK) {
        int base = blockIdx.x * ETILE;
        int e0r[2], e1r[2], gr[2]; float wr[2];
        #pragma unroll
        for (int j = 0; j < 2; j++) {
            int i = base + t + j * 256;
            if (i < Ee) {
                e0r[j] = ei[i]; e1r[j] = ei[Ee + i]; wr[j] = ew[i];
                gr[j] = bid[e0r[j]];
                atomicAdd(&scnt[gr[j]], 1);
            } else gr[j] = -1;
        }
        __syncthreads();
        if (t < Gg && scnt[t]) sbase[t] = atomicAdd(&d_ecur[t], scnt[t]);
        __syncthreads();
        #pragma unroll
        for (int j = 0; j < 2; j++) if (gr[j] >= 0) {
            int pos = sbase[gr[j]] + atomicAdd(&sloc[gr[j]], 1);
            d_epk[pos] = make_int4(e0r[j], e1r[j], gr[j], __float_as_int(wr[j]));
        }
    } else {
        int base = (blockIdx.x - EBLK) * ETILE;
        int f0r[2], f1r[2], f2r[2], gr[2]; float wr[2];
        #pragma unroll
        for (int j = 0; j < 2; j++) {
            int i = base + t + j * 256;
            if (i < Ff) {
                f0r[j] = fc[i]; f1r[j] = fc[Ff + i]; f2r[j] = fc[2 * Ff + i]; wr[j] = fw[i];
                gr[j] = bid[f0r[j]];
                atomicAdd(&scnt[gr[j]], 1);
            } else gr[j] = -1;
        }
        __syncthreads();
        if (t < Gg && scnt[t]) sbase[t] = atomicAdd(&d_fcur[t], scnt[t]);
        __syncthreads();
        #pragma unroll
        for (int j = 0; j < 2; j++) if (gr[j] >= 0) {
            int pos = sbase[gr[j]] + atomicAdd(&sloc[gr[j]], 1);
            d_fpk[pos] = make_int4(f0r[j], f1r[j], f2r[j], gr[j]);
            d_fsw[pos] = wr[j];
        }
    }
}

__device__ __forceinline__ float tanha(float z) {
    float r;
    asm("tanh.approx.f32 %0, %1;" : "=f"(r) : "f"(z));
    return r;
}

#define CL(b) (50.f * (-1.f + (2.f / 31.f) * (float)(b)))

// ---------------- launch 5: main ECC accumulation ----------------
// lane = direction (within a 32-dir half); 32 bumps in registers; no shfl, no smem.
// Element records broadcast-load; nh row loads coalesced; flush at graph boundary
// (warp-uniform) via coalesced atomicAdd.
__global__ void __launch_bounds__(TMAIN) main_kernel(const int* __restrict__ bid) {
    const int wid  = blockIdx.x * (TMAIN / 32) + (threadIdx.x >> 5);
    const int lane = threadIdx.x & 31;
    if (wid >= 2 * TOTS) return;
    const int doff = (wid & 1) * 32 + lane;
    int s = wid >> 1;
    int stream, strip;
    if (s < NSN)            { stream = 0; strip = s; }
    else if (s < NSN + NSE) { stream = 1; strip = s - NSN; }
    else                    { stream = 2; strip = s - NSN - NSE; }

    const int begin = strip * STRIP;
    const float* __restrict__ nhf = (const float*)d_nh4;
    const float sign = (stream == 1) ? -1.f : 1.f;

    float acc[NBUMP];
    #pragma unroll
    for (int b = 0; b < NBUMP; b++) acc[b] = 0.f;
    int gcur = -1;

    #define FLUSH() do {                                                      \
        float* p = &d_accS[gcur * (NBUMP * Dd) + doff];                       \
        _Pragma("unroll")                                                     \
        for (int b = 0; b < NBUMP; b++) {                                     \
            atomicAdd(p + b * Dd, sign * acc[b]); acc[b] = 0.f;               \
        } } while (0)

    for (int base = begin; base < begin + STRIP; base += 4) {
        float t4[4]; int g4[4];
        #pragma unroll
        for (int j = 0; j < 4; j++) {
            int i = base + j;
            if (stream == 0) {
                g4[j] = bid[i];
                t4[j] = 50.f * nhf[i * 64 + doff];
            } else if (stream == 1) {
                int4 e = d_epk[i];
                g4[j] = e.z;
                t4[j] = fmaxf(nhf[e.x * 64 + doff], nhf[e.y * 64 + doff])
                        * (50.f * __int_as_float(e.w));
            } else {
                int4 f = d_fpk[i];
                g4[j] = f.w;
                t4[j] = fmaxf(fmaxf(nhf[f.x * 64 + doff], nhf[f.y * 64 + doff]),
                              nhf[f.z * 64 + doff]) * (50.f * d_fsw[i]);
            }
        }
        #pragma unroll
        for (int j = 0; j < 4; j++) {
            if (g4[j] != gcur) {              // warp-uniform branch
                if (gcur >= 0) FLUSH();
                gcur = g4[j];
            }
            float t = t4[j];
            #pragma unroll
            for (int b = 0; b < NBUMP; b++) {
                acc[b] += tanha(CL(b) - t);   // 32 independent MUFU chains
            }
        }
    }
    if (gcur >= 0) FLUSH();
    #undef FLUSH
}

// ---------------- launch 6: finalize ecc + MLP, fused ----------------
__global__ void mlp_kernel(const float* __restrict__ W1, const float* __restrict__ b1,
                           const float* __restrict__ W2, const float* __restrict__ b2,
                           float* __restrict__ out) {
    __shared__ float sflat[NBUMP * Dd];
    __shared__ float sh[HIDN];
    int g = blockIdx.x;
    float halfnet = 0.5f * (float)d_netc[g];
    float* flat_out = out + Gg * NCLS + g * (NBUMP * Dd);
    const float* acc = d_accS + g * (NBUMP * Dd);
    for (int i = threadIdx.x; i < NBUMP * Dd; i += blockDim.x) {
        float val = halfnet + 0.5f * acc[i];
        sflat[i] = val;
        flat_out[i] = val;
    }
    __syncthreads();

    int warp = threadIdx.x >> 5, lane = threadIdx.x & 31;
    for (int hh = warp; hh < HIDN; hh += 8) {
        const float* wrow = W1 + hh * (NBUMP * Dd);
        float p = 0.f;
        #pragma unroll 8
        for (int k = lane; k < NBUMP * Dd; k += 32) p += wrow[k] * sflat[k];
        #pragma unroll
        for (int o = 16; o; o >>= 1) p += __shfl_down_sync(0xffffffffu, p, o);
        if (lane == 0) sh[hh] = fmaxf(p + b1[hh], 0.f);
    }
    __syncthreads();
    if (warp == 0) {
        for (int c = 0; c < NCLS; c++) {
            float p = 0.f;
            #pragma unroll
            for (int k = lane; k < HIDN; k += 32) p += W2[c * HIDN + k] * sh[k];
            #pragma unroll
            for (int o = 16; o; o >>= 1) p += __shfl_down_sync(0xffffffffu, p, o);
            if (lane == 0) out[g * NCLS + c] = p + b2[c];
        }
    }
}

// ---------------- launch ----------------
extern "C" void kernel_launch(void* const* d_in, const int* in_sizes, int n_in,
                              void* d_out, int out_size) {
    const float* x   = (const float*)d_in[0];
    const float* nw  = (const float*)d_in[1];
    const float* ew  = (const float*)d_in[2];
    const float* fw  = (const float*)d_in[3];
    const float* v   = (const float*)d_in[4];
    const float* W1  = (const float*)d_in[5];
    const float* b1  = (const float*)d_in[6];
    const float* W2  = (const float*)d_in[7];
    const float* b2  = (const float*)d_in[8];
    const int*   ei  = (const int*)d_in[9];
    const int*   fc  = (const int*)d_in[10];
    const int*   bid = (const int*)d_in[11];
    float* out = (float*)d_out;

    nh_kernel<<<(Nn + 255) / 256, 256>>>(x, nw, v);
    prep_kernel<<<128, 256>>>(bid, ei, fc);
    scan_kernel<<<1, 32>>>();
    scatter_kernel<<<EBLK + FBLK, 256>>>(ei, ew, fc, fw, bid);

    main_kernel<<<(2 * TOTS + (TMAIN / 32) - 1) / (TMAIN / 32), TMAIN>>>(bid);

    mlp_kernel<<<Gg, 256>>>(W1, b1, W2, b2, out);
}